// round 13
// baseline (speedup 1.0000x reference)
#include <cuda_runtime.h>
#include <cstdint>

#define IMG_H 512
#define IMG_W 512
#define TILE_H 16
#define NTHREADS 256   // thread owns cols 2t, 2t+1

__device__ __forceinline__ int reflr(int g) {
    // reflect-101: -1 -> 1, -2 -> 2, 512 -> 510, 513 -> 509
    g = g < 0 ? -g : g;
    if (g >= IMG_H) g = 2 * IMG_H - 2 - g;
    return g;
}

// L2 access policy: evict_last for the input stream (created once per thread).
__device__ __forceinline__ uint64_t mkpolicy() {
    uint64_t pol;
    asm("createpolicy.fractional.L2::evict_last.b64 %0, 1.0;" : "=l"(pol));
    return pol;
}

// Read-only load with evict-last L2 hint: keep input resident against the
// output write stream (stored evict-first via __stcs).
__device__ __forceinline__ float2 ld2_keep(const float* p, uint64_t pol) {
    float2 v;
    asm("ld.global.nc.L2::cache_hint.v2.f32 {%0, %1}, [%2], %3;"
        : "=f"(v.x), "=f"(v.y) : "l"(p), "l"(pol));
    return v;
}

// Load the 3 float2's needed for cols c,c+1 of one source row.
__device__ __forceinline__ void ldrow(const float* __restrict__ rp, int c0,
                                      bool isL, bool isR, uint64_t pol,
                                      float2& A, float2& B, float2& C)
{
    A = isL ? make_float2(0.f, 0.f) : ld2_keep(rp + c0 - 2, pol);
    B = ld2_keep(rp + c0, pol);
    C = isR ? make_float2(0.f, 0.f) : ld2_keep(rp + c0 + 2, pol);
}

// Horizontal 5-tap sums from A=(c-2,c-1), B=(c,c+1), C=(c+2,c+3).
// Edge lanes patch by register rename (reflect-101 identity):
//   t=0:   A=(C.x,B.y)   [cols -2,-1 -> 2,1]
//   t=255: C=(B.x,A.y)   [cols 512,513 -> 510,509]
__device__ __forceinline__ float2 hsum2(float2 A, float2 B, float2 C,
                                        bool isL, bool isR)
{
    if (isL) { A.x = C.x; A.y = B.y; }
    if (isR) { C.x = B.x; C.y = A.y; }
    float u = A.y + B.x + B.y + C.x;
    return make_float2(u + A.x, u + C.y);
}

__global__ __launch_bounds__(NTHREADS, 8)
void smooth5_kernel(const float* __restrict__ in, float* __restrict__ out)
{
    const int tid   = threadIdx.x;
    const int c0    = 2 * tid;
    const int plane = blockIdx.y;
    const int row0  = blockIdx.x * TILE_H;

    const float* ip = in  + (size_t)plane * (IMG_H * IMG_W);
    float*       op = out + (size_t)plane * (IMG_H * IMG_W);

    const bool isL = (tid == 0);
    const bool isR = (tid == NTHREADS - 1);
    const uint64_t pol = mkpolicy();

    // Warm-up: horizontal sums of source rows row0-2 .. row0+1 (top reflected)
    float2 A, B, C;
    ldrow(ip + (size_t)reflr(row0 - 2) * IMG_W, c0, isL, isR, pol, A, B, C);
    float2 h0 = hsum2(A, B, C, isL, isR);
    ldrow(ip + (size_t)reflr(row0 - 1) * IMG_W, c0, isL, isR, pol, A, B, C);
    float2 h1 = hsum2(A, B, C, isL, isR);
    ldrow(ip + (size_t)(row0) * IMG_W, c0, isL, isR, pol, A, B, C);
    float2 h2 = hsum2(A, B, C, isL, isR);
    ldrow(ip + (size_t)(row0 + 1) * IMG_W, c0, isL, isR, pol, A, B, C);
    float2 h3 = hsum2(A, B, C, isL, isR);

    const float inv25 = 1.0f / 25.0f;

    if (row0 + TILE_H + 2 <= IMG_H) {
        // ---------- interior fast path ----------
        const float* sp = ip + (size_t)(row0 + 2) * IMG_W;
        float*       dp = op + (size_t)(row0)     * IMG_W + c0;
        #pragma unroll
        for (int r = 0; r < TILE_H; ++r) {
            float2 a, b, c;
            ldrow(sp, c0, isL, isR, pol, a, b, c);
            sp += IMG_W;
            float2 h = hsum2(a, b, c, isL, isR);
            float2 o;
            o.x = (h0.x + h1.x + h2.x + h3.x + h.x) * inv25;
            o.y = (h0.y + h1.y + h2.y + h3.y + h.y) * inv25;
            __stcs(reinterpret_cast<float2*>(dp), o);   // evict-first write stream
            dp += IMG_W;
            h0 = h1; h1 = h2; h2 = h3; h3 = h;
        }
    } else {
        // ---------- bottom tile: reflected row indexing ----------
        #pragma unroll
        for (int r = 0; r < TILE_H; ++r) {
            const float* rp = ip + (size_t)reflr(row0 + 2 + r) * IMG_W;
            float2 a, b, c;
            ldrow(rp, c0, isL, isR, pol, a, b, c);
            float2 h = hsum2(a, b, c, isL, isR);
            float2 o;
            o.x = (h0.x + h1.x + h2.x + h3.x + h.x) * inv25;
            o.y = (h0.y + h1.y + h2.y + h3.y + h.y) * inv25;
            __stcs(reinterpret_cast<float2*>(op + (size_t)(row0 + r) * IMG_W + c0), o);
            h0 = h1; h1 = h2; h2 = h3; h3 = h;
        }
    }
}

extern "C" void kernel_launch(void* const* d_in, const int* in_sizes, int n_in,
                              void* d_out, int out_size)
{
    const float* in  = (const float*)d_in[0];
    float*       out = (float*)d_out;
    int planes = in_sizes[0] / (IMG_H * IMG_W);   // B*C = 96
    dim3 grid(IMG_H / TILE_H, planes);             // 32 x 96 = 3072 blocks
    smooth5_kernel<<<grid, NTHREADS>>>(in, out);
}

// round 14
// speedup vs baseline: 1.0690x; 1.0690x over previous
#include <cuda_runtime.h>
#include <cstdint>

#define IMG_H 512
#define IMG_W 512
#define TILE_H 16
#define NTHREADS 256   // thread owns cols 2t, 2t+1

__device__ __forceinline__ int reflr(int g) {
    // reflect-101: -1 -> 1, -2 -> 2, 512 -> 510, 513 -> 509
    g = g < 0 ? -g : g;
    if (g >= IMG_H) g = 2 * IMG_H - 2 - g;
    return g;
}

// L2 access policy: evict_last for the input stream (created once per thread).
__device__ __forceinline__ uint64_t mkpolicy() {
    uint64_t pol;
    asm("createpolicy.fractional.L2::evict_last.b64 %0, 1.0;" : "=l"(pol));
    return pol;
}

// Read-only load with evict-last L2 hint: keep input resident against the
// output write stream (stored evict-first via __stcs).
__device__ __forceinline__ float2 ld2_keep(const float* p, uint64_t pol) {
    float2 v;
    asm("ld.global.nc.L2::cache_hint.v2.f32 {%0, %1}, [%2], %3;"
        : "=f"(v.x), "=f"(v.y) : "l"(p), "l"(pol));
    return v;
}

struct Row { float2 A, B, C; };

// Load the 3 float2's needed for cols c,c+1 of one source row.
__device__ __forceinline__ Row ldrow(const float* __restrict__ rp, int c0,
                                     bool isL, bool isR, uint64_t pol)
{
    Row r;
    r.A = isL ? make_float2(0.f, 0.f) : ld2_keep(rp + c0 - 2, pol);
    r.B = ld2_keep(rp + c0, pol);
    r.C = isR ? make_float2(0.f, 0.f) : ld2_keep(rp + c0 + 2, pol);
    return r;
}

// Horizontal 5-tap sums from A=(c-2,c-1), B=(c,c+1), C=(c+2,c+3).
// Edge lanes patch by register rename (reflect-101 identity):
//   t=0:   A=(C.x,B.y)   [cols -2,-1 -> 2,1]
//   t=255: C=(B.x,A.y)   [cols 512,513 -> 510,509]
__device__ __forceinline__ float2 hsum2(Row r, bool isL, bool isR)
{
    float2 A = r.A, B = r.B, C = r.C;
    if (isL) { A.x = C.x; A.y = B.y; }
    if (isR) { C.x = B.x; C.y = A.y; }
    float u = A.y + B.x + B.y + C.x;
    return make_float2(u + A.x, u + C.y);
}

__global__ __launch_bounds__(NTHREADS, 5)
void smooth5_kernel(const float* __restrict__ in, float* __restrict__ out)
{
    const int tid   = threadIdx.x;
    const int c0    = 2 * tid;
    const int plane = blockIdx.y;
    const int row0  = blockIdx.x * TILE_H;

    const float* ip = in  + (size_t)plane * (IMG_H * IMG_W);
    float*       op = out + (size_t)plane * (IMG_H * IMG_W);

    const bool isL = (tid == 0);
    const bool isR = (tid == NTHREADS - 1);
    const uint64_t pol = mkpolicy();

    // Warm-up: horizontal sums of source rows row0-2 .. row0+1 (top reflected)
    float2 h0 = hsum2(ldrow(ip + (size_t)reflr(row0 - 2) * IMG_W, c0, isL, isR, pol), isL, isR);
    float2 h1 = hsum2(ldrow(ip + (size_t)reflr(row0 - 1) * IMG_W, c0, isL, isR, pol), isL, isR);
    float2 h2 = hsum2(ldrow(ip + (size_t)(row0)          * IMG_W, c0, isL, isR, pol), isL, isR);
    float2 h3 = hsum2(ldrow(ip + (size_t)(row0 + 1)      * IMG_W, c0, isL, isR, pol), isL, isR);

    const float inv25 = 1.0f / 25.0f;

    if (row0 + TILE_H + 2 <= IMG_H) {
        // ---------- interior fast path: depth-2 load pipeline ----------
        const float* sp = ip + (size_t)(row0 + 2) * IMG_W;
        float*       dp = op + (size_t)(row0)     * IMG_W + c0;

        Row p0 = ldrow(sp, c0, isL, isR, pol); sp += IMG_W;   // row row0+2
        Row p1 = ldrow(sp, c0, isL, isR, pol); sp += IMG_W;   // row row0+3

        #pragma unroll
        for (int r = 0; r < TILE_H; ++r) {
            Row cur = p0;
            p0 = p1;
            if (r < TILE_H - 2) {                              // prefetch row r+4
                p1 = ldrow(sp, c0, isL, isR, pol);
                sp += IMG_W;
            }
            float2 h = hsum2(cur, isL, isR);
            float2 o;
            o.x = (h0.x + h1.x + h2.x + h3.x + h.x) * inv25;
            o.y = (h0.y + h1.y + h2.y + h3.y + h.y) * inv25;
            __stcs(reinterpret_cast<float2*>(dp), o);          // evict-first writes
            dp += IMG_W;
            h0 = h1; h1 = h2; h2 = h3; h3 = h;
        }
    } else {
        // ---------- bottom tile: reflected row indexing ----------
        #pragma unroll
        for (int r = 0; r < TILE_H; ++r) {
            const float* rp = ip + (size_t)reflr(row0 + 2 + r) * IMG_W;
            float2 h = hsum2(ldrow(rp, c0, isL, isR, pol), isL, isR);
            float2 o;
            o.x = (h0.x + h1.x + h2.x + h3.x + h.x) * inv25;
            o.y = (h0.y + h1.y + h2.y + h3.y + h.y) * inv25;
            __stcs(reinterpret_cast<float2*>(op + (size_t)(row0 + r) * IMG_W + c0), o);
            h0 = h1; h1 = h2; h2 = h3; h3 = h;
        }
    }
}

extern "C" void kernel_launch(void* const* d_in, const int* in_sizes, int n_in,
                              void* d_out, int out_size)
{
    const float* in  = (const float*)d_in[0];
    float*       out = (float*)d_out;
    int planes = in_sizes[0] / (IMG_H * IMG_W);   // B*C = 96
    dim3 grid(IMG_H / TILE_H, planes);             // 32 x 96 = 3072 blocks
    smooth5_kernel<<<grid, NTHREADS>>>(in, out);
}